// round 1
// baseline (speedup 1.0000x reference)
#include <cuda_runtime.h>
#include <math.h>

#define MAXN 100000
#define MAXE 1600000

// ---------------- scratch (static __device__, no runtime allocation) ----------------
__device__ int   g_indeg[MAXN];
__device__ int   g_rowstart[MAXN];
__device__ int   g_cursor[MAXN];
__device__ int   g_bsum[256];
__device__ float g_dis[MAXN];
__device__ int   g_csr_src[MAXE];
__device__ float g_csr_w[MAXE];
__device__ float g_h0[(size_t)MAXN * 64];
__device__ float g_h [(size_t)MAXN * 64];
__device__ float g_gg[(size_t)MAXN * 64];
__device__ float g_z [(size_t)MAXN * 32];

// ---------------- graph preprocessing ----------------
__global__ void init_kernel(int n) {
    int i = blockIdx.x * blockDim.x + threadIdx.x;
    if (i < n) g_indeg[i] = 0;
}

__global__ void hist_kernel(const int* __restrict__ dst, int E) {
    int e = blockIdx.x * blockDim.x + threadIdx.x;
    if (e < E) atomicAdd(&g_indeg[dst[e]], 1);
}

__global__ void dis_kernel(int n) {
    int i = blockIdx.x * blockDim.x + threadIdx.x;
    if (i < n) g_dis[i] = rsqrtf((float)(g_indeg[i] + 1));   // deg includes self-loop
}

__global__ void scan1_kernel(int n) {
    __shared__ int sm[1024];
    int t = threadIdx.x;
    int i = blockIdx.x * 1024 + t;
    int v = (i < n) ? g_indeg[i] : 0;
    sm[t] = v;
    __syncthreads();
#pragma unroll
    for (int o = 1; o < 1024; o <<= 1) {
        int tv = (t >= o) ? sm[t - o] : 0;
        __syncthreads();
        sm[t] += tv;
        __syncthreads();
    }
    if (i < n) g_rowstart[i] = sm[t] - v;   // exclusive
    if (t == 1023) g_bsum[blockIdx.x] = sm[1023];
}

__global__ void scan2_kernel(int nb) {
    if (blockIdx.x == 0 && threadIdx.x == 0) {
        int run = 0;
        for (int b = 0; b < nb; b++) { int t = g_bsum[b]; g_bsum[b] = run; run += t; }
    }
}

__global__ void scan3_kernel(int n) {
    int i = blockIdx.x * blockDim.x + threadIdx.x;
    if (i < n) {
        int v = g_rowstart[i] + g_bsum[i >> 10];
        g_rowstart[i] = v;
        g_cursor[i]   = v;
    }
}

__global__ void fill_kernel(const int* __restrict__ src, const int* __restrict__ dst, int E) {
    int e = blockIdx.x * blockDim.x + threadIdx.x;
    if (e < E) {
        int d = dst[e];
        int s = src[e];
        int p = atomicAdd(&g_cursor[d], 1);
        g_csr_src[p] = s;
        g_csr_w[p]   = g_dis[s];
    }
}

// ---------------- GEMM 1: h0 = x[N,128] @ W1[128,64] ----------------
__global__ void __launch_bounds__(256) gemm1_kernel(const float* __restrict__ x,
                                                    const float* __restrict__ W, int n) {
    __shared__ float wsa[128 * 32];
    __shared__ float wsb[128 * 32];
    __shared__ float xsT[128 * 32];
    int tid = threadIdx.x;
    for (int i = tid; i < 128 * 64; i += 256) {
        int k = i >> 6, j = i & 63;
        float v = W[i];
        int jt = j >> 3, c = j & 7;
        if (c < 4) wsa[k * 32 + jt * 4 + c] = v;
        else       wsb[k * 32 + jt * 4 + (c - 4)] = v;
    }
    int row0 = blockIdx.x * 32;
    for (int i = tid; i < 4096; i += 256) {
        int r = i >> 7, k = i & 127;
        int row = row0 + r;
        xsT[k * 32 + r] = (row < n) ? x[(size_t)row * 128 + k] : 0.f;
    }
    __syncthreads();
    int lane = tid & 31, wrp = tid >> 5;
    int r  = wrp * 4 + (lane >> 3);
    int jt = lane & 7;
    float acc[8];
#pragma unroll
    for (int i = 0; i < 8; i++) acc[i] = 0.f;
    const float4* wa = (const float4*)wsa + jt;
    const float4* wb = (const float4*)wsb + jt;
#pragma unroll 8
    for (int k = 0; k < 128; k++) {
        float xf = xsT[k * 32 + r];
        float4 a = wa[k * 8];
        float4 b = wb[k * 8];
        acc[0] = fmaf(xf, a.x, acc[0]); acc[1] = fmaf(xf, a.y, acc[1]);
        acc[2] = fmaf(xf, a.z, acc[2]); acc[3] = fmaf(xf, a.w, acc[3]);
        acc[4] = fmaf(xf, b.x, acc[4]); acc[5] = fmaf(xf, b.y, acc[5]);
        acc[6] = fmaf(xf, b.z, acc[6]); acc[7] = fmaf(xf, b.w, acc[7]);
    }
    int row = row0 + r;
    if (row < n) {
        float4* o = (float4*)(g_h0 + (size_t)row * 64 + jt * 8);
        o[0] = make_float4(acc[0], acc[1], acc[2], acc[3]);
        o[1] = make_float4(acc[4], acc[5], acc[6], acc[7]);
    }
}

// ---------------- GEMM 2: gg = h[N,64] @ [Wmu|Wls][64,64] ----------------
__global__ void __launch_bounds__(256) gemm2_kernel(const float* __restrict__ Wmu,
                                                    const float* __restrict__ Wls, int n) {
    __shared__ float wsa[64 * 32];
    __shared__ float wsb[64 * 32];
    __shared__ float xsT[64 * 32];
    int tid = threadIdx.x;
    for (int i = tid; i < 64 * 64; i += 256) {
        int k = i >> 6, j = i & 63;
        float v = (j < 32) ? Wmu[k * 32 + j] : Wls[k * 32 + (j - 32)];
        int jt = j >> 3, c = j & 7;
        if (c < 4) wsa[k * 32 + jt * 4 + c] = v;
        else       wsb[k * 32 + jt * 4 + (c - 4)] = v;
    }
    int row0 = blockIdx.x * 32;
    for (int i = tid; i < 2048; i += 256) {
        int r = i >> 6, k = i & 63;
        int row = row0 + r;
        xsT[k * 32 + r] = (row < n) ? g_h[(size_t)row * 64 + k] : 0.f;
    }
    __syncthreads();
    int lane = tid & 31, wrp = tid >> 5;
    int r  = wrp * 4 + (lane >> 3);
    int jt = lane & 7;
    float acc[8];
#pragma unroll
    for (int i = 0; i < 8; i++) acc[i] = 0.f;
    const float4* wa = (const float4*)wsa + jt;
    const float4* wb = (const float4*)wsb + jt;
#pragma unroll 8
    for (int k = 0; k < 64; k++) {
        float xf = xsT[k * 32 + r];
        float4 a = wa[k * 8];
        float4 b = wb[k * 8];
        acc[0] = fmaf(xf, a.x, acc[0]); acc[1] = fmaf(xf, a.y, acc[1]);
        acc[2] = fmaf(xf, a.z, acc[2]); acc[3] = fmaf(xf, a.w, acc[3]);
        acc[4] = fmaf(xf, b.x, acc[4]); acc[5] = fmaf(xf, b.y, acc[5]);
        acc[6] = fmaf(xf, b.z, acc[6]); acc[7] = fmaf(xf, b.w, acc[7]);
    }
    int row = row0 + r;
    if (row < n) {
        float4* o = (float4*)(g_gg + (size_t)row * 64 + jt * 8);
        o[0] = make_float4(acc[0], acc[1], acc[2], acc[3]);
        o[1] = make_float4(acc[4], acc[5], acc[6], acc[7]);
    }
}

// ---------------- Conv1 gather + bias + relu + row L2 normalize ----------------
__global__ void __launch_bounds__(256) conv1_kernel(const float* __restrict__ b1, int n) {
    int unit = threadIdx.x >> 6;
    int j    = threadIdx.x & 63;
    int node = blockIdx.x * 4 + unit;
    __shared__ float red[4][2];
    float val = 0.f;
    if (node < n) {
        int st = g_rowstart[node], cnt = g_indeg[node];
        float acc = 0.f;
        for (int e = 0; e < cnt; e++) {
            int   s = g_csr_src[st + e];
            float w = g_csr_w[st + e];
            acc = fmaf(w, g_h0[(size_t)s * 64 + j], acc);
        }
        float di = g_dis[node];
        val = fmaf(di, acc, di * di * g_h0[(size_t)node * 64 + j]) + b1[j];
        val = fmaxf(val, 0.f);
    }
    float ss = val * val;
#pragma unroll
    for (int o = 16; o > 0; o >>= 1) ss += __shfl_xor_sync(0xffffffffu, ss, o);
    if ((threadIdx.x & 31) == 0) red[unit][(threadIdx.x >> 5) & 1] = ss;
    __syncthreads();
    if (node < n) {
        float tot   = red[unit][0] + red[unit][1];
        float scale = 1.0f / fmaxf(sqrtf(tot), 1e-12f);
        g_h[(size_t)node * 64 + j] = val * scale;
    }
}

// ---------------- Conv2 gather (mu | logstd fused) ----------------
__global__ void __launch_bounds__(256) conv2_kernel(const float* __restrict__ bmu,
                                                    const float* __restrict__ bls,
                                                    float* __restrict__ out_mu,
                                                    float* __restrict__ out_ls, int n) {
    int unit = threadIdx.x >> 6;
    int j    = threadIdx.x & 63;
    int node = blockIdx.x * 4 + unit;
    if (node >= n) return;
    int st = g_rowstart[node], cnt = g_indeg[node];
    float acc = 0.f;
    for (int e = 0; e < cnt; e++) {
        int   s = g_csr_src[st + e];
        float w = g_csr_w[st + e];
        acc = fmaf(w, g_gg[(size_t)s * 64 + j], acc);
    }
    float di  = g_dis[node];
    float val = fmaf(di, acc, di * di * g_gg[(size_t)node * 64 + j]);
    if (j < 32) out_mu[(size_t)node * 32 + j] = val + bmu[j];
    else        out_ls[(size_t)node * 32 + (j - 32)] = val + bls[j - 32];
}

// ---------------- reparametrize ----------------
__global__ void z_kernel(const float* __restrict__ eps, const float* __restrict__ mu,
                         const float* __restrict__ ls, int total) {
    int i = blockIdx.x * blockDim.x + threadIdx.x;
    if (i < total) {
        float l = ls[i];
        l = fminf(fmaxf(l, -10.f), 10.f);
        g_z[i] = fmaf(eps[i], expf(l), mu[i]);
    }
}

// ---------------- decode: sigmoid(<z_s, z_d>) over edges ----------------
__global__ void __launch_bounds__(256) decode_kernel(const int* __restrict__ src,
                                                     const int* __restrict__ dst,
                                                     float* __restrict__ out, int E) {
    int w    = (blockIdx.x * blockDim.x + threadIdx.x) >> 5;
    int lane = threadIdx.x & 31;
    if (w >= E) return;
    int s = src[w], d = dst[w];
    float p = g_z[(size_t)s * 32 + lane] * g_z[(size_t)d * 32 + lane];
#pragma unroll
    for (int o = 16; o > 0; o >>= 1) p += __shfl_xor_sync(0xffffffffu, p, o);
    if (lane == 0) out[w] = 1.0f / (1.0f + expf(-p));
}

// ---------------- launch ----------------
extern "C" void kernel_launch(void* const* d_in, const int* in_sizes, int n_in,
                              void* d_out, int out_size) {
    const float* x   = (const float*)d_in[0];
    const int*   ei  = (const int*)  d_in[1];
    const float* eps = (const float*)d_in[2];
    const float* W1  = (const float*)d_in[3];
    const float* b1  = (const float*)d_in[4];
    const float* Wmu = (const float*)d_in[5];
    const float* bmu = (const float*)d_in[6];
    const float* Wls = (const float*)d_in[7];
    const float* bls = (const float*)d_in[8];

    int n = in_sizes[0] / 128;
    int E = in_sizes[1] / 2;
    const int* src = ei;
    const int* dst = ei + E;

    float* out     = (float*)d_out;
    float* out_adj = out;
    float* out_mu  = out + E;
    float* out_ls  = out + E + (size_t)n * 32;

    init_kernel<<<(n + 255) / 256, 256>>>(n);
    hist_kernel<<<(E + 255) / 256, 256>>>(dst, E);
    dis_kernel<<<(n + 255) / 256, 256>>>(n);
    int nb = (n + 1023) / 1024;
    scan1_kernel<<<nb, 1024>>>(n);
    scan2_kernel<<<1, 32>>>(nb);
    scan3_kernel<<<(n + 255) / 256, 256>>>(n);
    fill_kernel<<<(E + 255) / 256, 256>>>(src, dst, E);

    gemm1_kernel<<<(n + 31) / 32, 256>>>(x, W1, n);
    conv1_kernel<<<(n + 3) / 4, 256>>>(b1, n);
    gemm2_kernel<<<(n + 31) / 32, 256>>>(Wmu, Wls, n);
    conv2_kernel<<<(n + 3) / 4, 256>>>(bmu, bls, out_mu, out_ls, n);
    z_kernel<<<((n * 32) + 255) / 256, 256>>>(eps, out_mu, out_ls, n * 32);
    decode_kernel<<<(E + 7) / 8, 256>>>(src, dst, out_adj, E);
}

// round 2
// speedup vs baseline: 1.4201x; 1.4201x over previous
#include <cuda_runtime.h>
#include <math.h>

#define MAXN 100000
#define MAXE 1600000

// ---------------- scratch ----------------
__device__ int   g_indeg[MAXN];
__device__ int   g_rowstart[MAXN];
__device__ int   g_cursor[MAXN];
__device__ int   g_bsum[256];
__device__ float g_dis[MAXN];
__device__ int2  g_csr[MAXE];            // {src, float-bits of dis[src]}
__device__ float g_h0[(size_t)MAXN * 64];
__device__ float g_h [(size_t)MAXN * 64];
__device__ float g_gg[(size_t)MAXN * 64];  // interleaved (mu_j, ls_j) pairs
__device__ float g_z [(size_t)MAXN * 32];

// ---------------- graph preprocessing ----------------
__global__ void init_kernel(int n) {
    int i = blockIdx.x * blockDim.x + threadIdx.x;
    if (i < n) g_indeg[i] = 0;
}

__global__ void hist_kernel(const int* __restrict__ dst, int E) {
    int e = blockIdx.x * blockDim.x + threadIdx.x;
    if (e < E) atomicAdd(&g_indeg[dst[e]], 1);
}

__global__ void scan1_kernel(int n) {
    __shared__ int sm[1024];
    int t = threadIdx.x;
    int i = blockIdx.x * 1024 + t;
    int v = (i < n) ? g_indeg[i] : 0;
    sm[t] = v;
    __syncthreads();
#pragma unroll
    for (int o = 1; o < 1024; o <<= 1) {
        int tv = (t >= o) ? sm[t - o] : 0;
        __syncthreads();
        sm[t] += tv;
        __syncthreads();
    }
    if (i < n) g_rowstart[i] = sm[t] - v;   // block-local exclusive
    if (t == 1023) g_bsum[blockIdx.x] = sm[1023];
}

// parallel block-sum exclusive scan (was serial single-thread: ~15us of latency)
__global__ void scan2_kernel(int nb) {
    __shared__ int sm[256];
    int t = threadIdx.x;
    int v = (t < nb) ? g_bsum[t] : 0;
    sm[t] = v;
    __syncthreads();
#pragma unroll
    for (int o = 1; o < 256; o <<= 1) {
        int tv = (t >= o) ? sm[t - o] : 0;
        __syncthreads();
        sm[t] += tv;
        __syncthreads();
    }
    if (t < nb) g_bsum[t] = sm[t] - v;      // exclusive
}

__global__ void scan3_kernel(int n) {
    int i = blockIdx.x * blockDim.x + threadIdx.x;
    if (i < n) {
        int v = g_rowstart[i] + g_bsum[i >> 10];
        g_rowstart[i] = v;
        g_cursor[i]   = v;
        g_dis[i]      = rsqrtf((float)(g_indeg[i] + 1));  // fused dis computation
    }
}

__global__ void fill_kernel(const int* __restrict__ src, const int* __restrict__ dst, int E) {
    int e = blockIdx.x * blockDim.x + threadIdx.x;
    if (e < E) {
        int d = dst[e];
        int s = src[e];
        int p = atomicAdd(&g_cursor[d], 1);
        g_csr[p] = make_int2(s, __float_as_int(g_dis[s]));
    }
}

// ---------------- GEMM 1: h0 = x[N,128] @ W1[128,64] ----------------
__global__ void __launch_bounds__(256) gemm1_kernel(const float* __restrict__ x,
                                                    const float* __restrict__ W, int n) {
    __shared__ float wsa[128 * 32];
    __shared__ float wsb[128 * 32];
    __shared__ float xsT[128 * 32];
    int tid = threadIdx.x;
    for (int i = tid; i < 128 * 64; i += 256) {
        int k = i >> 6, j = i & 63;
        float v = W[i];
        int jt = j >> 3, c = j & 7;
        if (c < 4) wsa[k * 32 + jt * 4 + c] = v;
        else       wsb[k * 32 + jt * 4 + (c - 4)] = v;
    }
    int row0 = blockIdx.x * 32;
    for (int i = tid; i < 4096; i += 256) {
        int r = i >> 7, k = i & 127;
        int row = row0 + r;
        xsT[k * 32 + r] = (row < n) ? x[(size_t)row * 128 + k] : 0.f;
    }
    __syncthreads();
    int lane = tid & 31, wrp = tid >> 5;
    int r  = wrp * 4 + (lane >> 3);
    int jt = lane & 7;
    float acc[8];
#pragma unroll
    for (int i = 0; i < 8; i++) acc[i] = 0.f;
    const float4* wa = (const float4*)wsa + jt;
    const float4* wb = (const float4*)wsb + jt;
#pragma unroll 8
    for (int k = 0; k < 128; k++) {
        float xf = xsT[k * 32 + r];
        float4 a = wa[k * 8];
        float4 b = wb[k * 8];
        acc[0] = fmaf(xf, a.x, acc[0]); acc[1] = fmaf(xf, a.y, acc[1]);
        acc[2] = fmaf(xf, a.z, acc[2]); acc[3] = fmaf(xf, a.w, acc[3]);
        acc[4] = fmaf(xf, b.x, acc[4]); acc[5] = fmaf(xf, b.y, acc[5]);
        acc[6] = fmaf(xf, b.z, acc[6]); acc[7] = fmaf(xf, b.w, acc[7]);
    }
    int row = row0 + r;
    if (row < n) {
        float4* o = (float4*)(g_h0 + (size_t)row * 64 + jt * 8);
        o[0] = make_float4(acc[0], acc[1], acc[2], acc[3]);
        o[1] = make_float4(acc[4], acc[5], acc[6], acc[7]);
    }
}

// ---------------- GEMM 2: gg = h[N,64] @ [Wmu|Wls] with (mu,ls) column interleave ----------------
__global__ void __launch_bounds__(256) gemm2_kernel(const float* __restrict__ Wmu,
                                                    const float* __restrict__ Wls, int n) {
    __shared__ float wsa[64 * 32];
    __shared__ float wsb[64 * 32];
    __shared__ float xsT[64 * 32];
    int tid = threadIdx.x;
    for (int i = tid; i < 64 * 64; i += 256) {
        int k = i >> 6, j = i & 63;
        float v = (j < 32) ? Wmu[k * 32 + j] : Wls[k * 32 + (j - 32)];
        int jn = (j < 32) ? (2 * j) : (2 * (j - 32) + 1);   // interleave mu/ls columns
        int jt = jn >> 3, c = jn & 7;
        if (c < 4) wsa[k * 32 + jt * 4 + c] = v;
        else       wsb[k * 32 + jt * 4 + (c - 4)] = v;
    }
    int row0 = blockIdx.x * 32;
    for (int i = tid; i < 2048; i += 256) {
        int r = i >> 6, k = i & 63;
        int row = row0 + r;
        xsT[k * 32 + r] = (row < n) ? g_h[(size_t)row * 64 + k] : 0.f;
    }
    __syncthreads();
    int lane = tid & 31, wrp = tid >> 5;
    int r  = wrp * 4 + (lane >> 3);
    int jt = lane & 7;
    float acc[8];
#pragma unroll
    for (int i = 0; i < 8; i++) acc[i] = 0.f;
    const float4* wa = (const float4*)wsa + jt;
    const float4* wb = (const float4*)wsb + jt;
#pragma unroll 8
    for (int k = 0; k < 64; k++) {
        float xf = xsT[k * 32 + r];
        float4 a = wa[k * 8];
        float4 b = wb[k * 8];
        acc[0] = fmaf(xf, a.x, acc[0]); acc[1] = fmaf(xf, a.y, acc[1]);
        acc[2] = fmaf(xf, a.z, acc[2]); acc[3] = fmaf(xf, a.w, acc[3]);
        acc[4] = fmaf(xf, b.x, acc[4]); acc[5] = fmaf(xf, b.y, acc[5]);
        acc[6] = fmaf(xf, b.z, acc[6]); acc[7] = fmaf(xf, b.w, acc[7]);
    }
    int row = row0 + r;
    if (row < n) {
        float4* o = (float4*)(g_gg + (size_t)row * 64 + jt * 8);
        o[0] = make_float4(acc[0], acc[1], acc[2], acc[3]);
        o[1] = make_float4(acc[4], acc[5], acc[6], acc[7]);
    }
}

// ---------------- Conv1: warp per node, float2 per lane, unroll-4 gather ----------------
__global__ void __launch_bounds__(256) conv1_kernel(const float* __restrict__ b1, int n) {
    int wrp = threadIdx.x >> 5;
    int t   = threadIdx.x & 31;
    int node = blockIdx.x * 8 + wrp;
    if (node >= n) return;
    int st  = g_rowstart[node];
    int cnt = g_indeg[node];
    const int2* cs = g_csr + st;
    float ax = 0.f, ay = 0.f;
    int e = 0;
    for (; e + 4 <= cnt; e += 4) {
        int2 r0 = cs[e], r1 = cs[e + 1], r2 = cs[e + 2], r3 = cs[e + 3];
        float2 v0 = *(const float2*)(g_h0 + (size_t)r0.x * 64 + 2 * t);
        float2 v1 = *(const float2*)(g_h0 + (size_t)r1.x * 64 + 2 * t);
        float2 v2 = *(const float2*)(g_h0 + (size_t)r2.x * 64 + 2 * t);
        float2 v3 = *(const float2*)(g_h0 + (size_t)r3.x * 64 + 2 * t);
        float w0 = __int_as_float(r0.y), w1 = __int_as_float(r1.y);
        float w2 = __int_as_float(r2.y), w3 = __int_as_float(r3.y);
        ax = fmaf(w0, v0.x, ax); ay = fmaf(w0, v0.y, ay);
        ax = fmaf(w1, v1.x, ax); ay = fmaf(w1, v1.y, ay);
        ax = fmaf(w2, v2.x, ax); ay = fmaf(w2, v2.y, ay);
        ax = fmaf(w3, v3.x, ax); ay = fmaf(w3, v3.y, ay);
    }
    for (; e < cnt; e++) {
        int2 r = cs[e];
        float2 v = *(const float2*)(g_h0 + (size_t)r.x * 64 + 2 * t);
        float w = __int_as_float(r.y);
        ax = fmaf(w, v.x, ax); ay = fmaf(w, v.y, ay);
    }
    float di = g_dis[node];
    float2 self = *(const float2*)(g_h0 + (size_t)node * 64 + 2 * t);
    float2 bb   = *(const float2*)(b1 + 2 * t);
    float vx = fmaxf(fmaf(di, ax, di * di * self.x) + bb.x, 0.f);
    float vy = fmaxf(fmaf(di, ay, di * di * self.y) + bb.y, 0.f);
    float ss = vx * vx + vy * vy;
#pragma unroll
    for (int o = 16; o > 0; o >>= 1) ss += __shfl_xor_sync(0xffffffffu, ss, o);
    float scale = 1.0f / fmaxf(sqrtf(ss), 1e-12f);
    float2* o = (float2*)(g_h + (size_t)node * 64 + 2 * t);
    *o = make_float2(vx * scale, vy * scale);
}

// ---------------- Conv2 (+ fused reparametrize): warp per node ----------------
__global__ void __launch_bounds__(256) conv2_kernel(const float* __restrict__ bmu,
                                                    const float* __restrict__ bls,
                                                    const float* __restrict__ eps,
                                                    float* __restrict__ out_mu,
                                                    float* __restrict__ out_ls, int n) {
    int wrp = threadIdx.x >> 5;
    int t   = threadIdx.x & 31;
    int node = blockIdx.x * 8 + wrp;
    if (node >= n) return;
    int st  = g_rowstart[node];
    int cnt = g_indeg[node];
    const int2* cs = g_csr + st;
    float ax = 0.f, ay = 0.f;
    int e = 0;
    for (; e + 4 <= cnt; e += 4) {
        int2 r0 = cs[e], r1 = cs[e + 1], r2 = cs[e + 2], r3 = cs[e + 3];
        float2 v0 = *(const float2*)(g_gg + (size_t)r0.x * 64 + 2 * t);
        float2 v1 = *(const float2*)(g_gg + (size_t)r1.x * 64 + 2 * t);
        float2 v2 = *(const float2*)(g_gg + (size_t)r2.x * 64 + 2 * t);
        float2 v3 = *(const float2*)(g_gg + (size_t)r3.x * 64 + 2 * t);
        float w0 = __int_as_float(r0.y), w1 = __int_as_float(r1.y);
        float w2 = __int_as_float(r2.y), w3 = __int_as_float(r3.y);
        ax = fmaf(w0, v0.x, ax); ay = fmaf(w0, v0.y, ay);
        ax = fmaf(w1, v1.x, ax); ay = fmaf(w1, v1.y, ay);
        ax = fmaf(w2, v2.x, ax); ay = fmaf(w2, v2.y, ay);
        ax = fmaf(w3, v3.x, ax); ay = fmaf(w3, v3.y, ay);
    }
    for (; e < cnt; e++) {
        int2 r = cs[e];
        float2 v = *(const float2*)(g_gg + (size_t)r.x * 64 + 2 * t);
        float w = __int_as_float(r.y);
        ax = fmaf(w, v.x, ax); ay = fmaf(w, v.y, ay);
    }
    float di = g_dis[node];
    float2 self = *(const float2*)(g_gg + (size_t)node * 64 + 2 * t);
    float mu = fmaf(di, ax, di * di * self.x) + bmu[t];
    float ls = fmaf(di, ay, di * di * self.y) + bls[t];
    size_t oi = (size_t)node * 32 + t;
    out_mu[oi] = mu;
    out_ls[oi] = ls;
    float lc = fminf(fmaxf(ls, -10.f), 10.f);
    g_z[oi] = fmaf(eps[oi], expf(lc), mu);
}

// ---------------- decode: 8 lanes per edge, float4 dot + 3 shuffles ----------------
__global__ void __launch_bounds__(256) decode_kernel(const int* __restrict__ src,
                                                     const int* __restrict__ dst,
                                                     float* __restrict__ out, int E) {
    int gid = blockIdx.x * 256 + threadIdx.x;
    int e   = gid >> 3;
    int sub = gid & 7;
    if (e >= E) return;
    int s = src[e], d = dst[e];
    float4 a = *(const float4*)(g_z + (size_t)s * 32 + sub * 4);
    float4 b = *(const float4*)(g_z + (size_t)d * 32 + sub * 4);
    float p = a.x * b.x + a.y * b.y + a.z * b.z + a.w * b.w;
    p += __shfl_xor_sync(0xffffffffu, p, 1);
    p += __shfl_xor_sync(0xffffffffu, p, 2);
    p += __shfl_xor_sync(0xffffffffu, p, 4);
    if (sub == 0) out[e] = 1.0f / (1.0f + expf(-p));
}

// ---------------- launch ----------------
extern "C" void kernel_launch(void* const* d_in, const int* in_sizes, int n_in,
                              void* d_out, int out_size) {
    const float* x   = (const float*)d_in[0];
    const int*   ei  = (const int*)  d_in[1];
    const float* eps = (const float*)d_in[2];
    const float* W1  = (const float*)d_in[3];
    const float* b1  = (const float*)d_in[4];
    const float* Wmu = (const float*)d_in[5];
    const float* bmu = (const float*)d_in[6];
    const float* Wls = (const float*)d_in[7];
    const float* bls = (const float*)d_in[8];

    int n = in_sizes[0] / 128;
    int E = in_sizes[1] / 2;
    const int* src = ei;
    const int* dst = ei + E;

    float* out     = (float*)d_out;
    float* out_adj = out;
    float* out_mu  = out + E;
    float* out_ls  = out + E + (size_t)n * 32;

    init_kernel<<<(n + 255) / 256, 256>>>(n);
    hist_kernel<<<(E + 255) / 256, 256>>>(dst, E);
    int nb = (n + 1023) / 1024;
    scan1_kernel<<<nb, 1024>>>(n);
    scan2_kernel<<<1, 256>>>(nb);
    scan3_kernel<<<(n + 255) / 256, 256>>>(n);
    fill_kernel<<<(E + 255) / 256, 256>>>(src, dst, E);

    gemm1_kernel<<<(n + 31) / 32, 256>>>(x, W1, n);
    conv1_kernel<<<(n + 7) / 8, 256>>>(b1, n);
    gemm2_kernel<<<(n + 31) / 32, 256>>>(Wmu, Wls, n);
    conv2_kernel<<<(n + 7) / 8, 256>>>(bmu, bls, eps, out_mu, out_ls, n);
    decode_kernel<<<((size_t)E * 8 + 255) / 256, 256>>>(src, dst, out_adj, E);
}